// round 8
// baseline (speedup 1.0000x reference)
#include <cuda_runtime.h>
#include <math.h>

// Problem constants
#define B_   1024
#define L_   50
#define H_   256
#define N_   100000
#define A_   100
#define NN_  99999   // N-1 score columns

// Scratch: final_rep [B, H]  (1 MB, __device__ global per allocation rules)
__device__ float g_final_rep[B_ * H_];

// ---------------------------------------------------------------------------
// Kernel 1: per-batch fused pipeline
//   gather x -> Q,K (sigmoid GEMMs) -> affinity (written to out) ->
//   item_score -> softmax -> att -> final_rep (to scratch)
// One CTA per batch row, 256 threads, ~104 KB dynamic smem.
// ---------------------------------------------------------------------------
__global__ void __launch_bounds__(256) k1_kernel(
    const int*   __restrict__ inputs,
    const float* __restrict__ masks,
    const float* __restrict__ emb,
    const float* __restrict__ Qw,
    const float* __restrict__ Kw,
    const float* __restrict__ lin_w,
    const float* __restrict__ lin_b,
    float*       __restrict__ out_aff)
{
    extern __shared__ float sm[];
    float* s_x     = sm;                    // L*H   = 12800
    float* s_Q     = s_x   + L_ * H_;       // L*A   = 5000
    float* s_K     = s_Q   + L_ * A_;       // 5000
    float* s_aff   = s_K   + L_ * A_;       // L*L   = 2500
    float* s_score = s_aff + L_ * L_;       // 64
    float* s_att   = s_score + 64;          // 256
    float* s_last  = s_att   + H_;          // 256
    float* s_mask  = s_last  + H_;          // 64
    int*   s_idx   = (int*)(s_mask + 64);   // 64
    int*   s_misc  = s_idx + 64;            // [0] = last_id

    const int b   = blockIdx.x;
    const int tid = threadIdx.x;

    if (tid < L_) {
        s_idx[tid]  = inputs[b * L_ + tid];
        s_mask[tid] = masks[b * L_ + tid];
    }
    __syncthreads();

    // gather x = emb[inputs[b]]  (vectorized)
    for (int i = tid; i < L_ * (H_ / 4); i += 256) {
        int l = i / (H_ / 4);
        ((float4*)s_x)[i] = ((const float4*)emb)[s_idx[l] * (H_ / 4) + (i - l * (H_ / 4))];
    }
    __syncthreads();

    // Q = sigmoid(x @ Qw^T), K = sigmoid(x @ Kw^T)   [L, A]
    for (int p = tid; p < L_ * A_; p += 256) {
        int l = p / A_;
        int a = p - l * A_;
        const float4* xr = (const float4*)(s_x + l * H_);
        const float4* qr = (const float4*)(Qw + a * H_);
        const float4* kr = (const float4*)(Kw + a * H_);
        float aq = 0.f, ak = 0.f;
#pragma unroll 16
        for (int c = 0; c < H_ / 4; c++) {
            float4 x4 = xr[c], q4 = qr[c], k4 = kr[c];
            aq += x4.x * q4.x + x4.y * q4.y + x4.z * q4.z + x4.w * q4.w;
            ak += x4.x * k4.x + x4.y * k4.y + x4.z * k4.z + x4.w * k4.w;
        }
        s_Q[p] = 1.f / (1.f + expf(-aq));
        s_K[p] = 1.f / (1.f + expf(-ak));
    }
    __syncthreads();

    // affinity[l,m] = dot(Q[l], K[m]) / sqrt(A)   (full, incl. diagonal) -> output #2
    for (int p = tid; p < L_ * L_; p += 256) {
        int l = p / L_;
        int m = p - l * L_;
        const float4* qr = (const float4*)(s_Q + l * A_);
        const float4* kr = (const float4*)(s_K + m * A_);
        float acc = 0.f;
#pragma unroll
        for (int c = 0; c < A_ / 4; c++) {
            float4 q4 = qr[c], k4 = kr[c];
            acc += q4.x * k4.x + q4.y * k4.y + q4.z * k4.z + q4.w * k4.w;
        }
        acc *= 0.1f;   // 1/sqrt(100)
        s_aff[p] = acc;
        out_aff[(long)b * (L_ * L_) + p] = acc;
    }
    __syncthreads();

    // item_score[l] = (sum_m aff*mask[m] - diag) * mask[l]
    if (tid < L_) {
        float s = 0.f;
        for (int m = 0; m < L_; m++) s += s_aff[tid * L_ + m] * s_mask[m];
        s -= s_aff[tid * L_ + tid] * s_mask[tid];
        s_score[tid] = s * s_mask[tid];
    }
    __syncthreads();

    // softmax (max-subtracted), *mask, renormalize; also last_id
    if (tid == 0) {
        float mx = -1e30f;
        for (int l = 0; l < L_; l++) mx = fmaxf(mx, s_score[l]);
        float sum = 0.f;
        for (int l = 0; l < L_; l++) {
            float e = expf(s_score[l] - mx) * s_mask[l];
            s_aff[l] = e;          // reuse s_aff as temp
            sum += e;
        }
        float inv = 1.f / sum;
        for (int l = 0; l < L_; l++) s_score[l] = s_aff[l] * inv;
        float fl = 0.f;
        for (int m = 0; m < L_; m++) fl += s_mask[m];
        int len = (int)fl;
        s_misc[0] = s_idx[len - 1];
    }
    __syncthreads();

    // att[h] = sum_l score[l]*x[l,h]; last_emb gather
    const int last_id = s_misc[0];
    s_last[tid] = emb[(long)last_id * H_ + tid];
    float att = 0.f;
#pragma unroll 10
    for (int l = 0; l < L_; l++) att += s_score[l] * s_x[l * H_ + tid];
    s_att[tid] = att;
    __syncthreads();

    // final_rep[h] = [att|last] . lin_w[h,:] + lin_b[h]
    float acc = lin_b[tid];
    const float4* w  = (const float4*)(lin_w + tid * (2 * H_));
    const float4* a4 = (const float4*)s_att;
    const float4* l4 = (const float4*)s_last;
#pragma unroll 8
    for (int c = 0; c < H_ / 4; c++) {
        float4 wv = w[c], av = a4[c];
        acc += wv.x * av.x + wv.y * av.y + wv.z * av.z + wv.w * av.w;
    }
#pragma unroll 8
    for (int c = 0; c < H_ / 4; c++) {
        float4 wv = w[H_ / 4 + c], lv = l4[c];
        acc += wv.x * lv.x + wv.y * lv.y + wv.z * lv.z + wv.w * lv.w;
    }
    g_final_rep[b * H_ + tid] = acc;
}

// ---------------------------------------------------------------------------
// Kernel 2: scores[b,n] = dot(final_rep[b], emb[n+1])
//   M=1024, N=99999, K=256.  128x128x32 tile, 256 threads, 8x8 per thread.
// ---------------------------------------------------------------------------
#define BM 128
#define BN 128
#define BK 32

__global__ void __launch_bounds__(256, 2) k2_kernel(
    const float* __restrict__ emb,
    float*       __restrict__ out)
{
    __shared__ float Asm[BK][BM];
    __shared__ float Bsm[BK][BN];

    const int n0 = blockIdx.x * BN;
    const int m0 = blockIdx.y * BM;
    const int tid = threadIdx.x;
    const int tx = tid & 15;        // n dir
    const int ty = tid >> 4;        // m dir

    float acc[8][8];
#pragma unroll
    for (int i = 0; i < 8; i++)
#pragma unroll
        for (int j = 0; j < 8; j++) acc[i][j] = 0.f;

    const float* Amat = g_final_rep;

    for (int kc = 0; kc < H_; kc += BK) {
#pragma unroll
        for (int i = 0; i < 4; i++) {
            int v   = tid + i * 256;     // 0..1023
            int row = v >> 3;            // 0..127
            int c4  = (v & 7) * 4;       // k within chunk
            float4 av = *(const float4*)(Amat + (m0 + row) * H_ + kc + c4);
            Asm[c4 + 0][row] = av.x;
            Asm[c4 + 1][row] = av.y;
            Asm[c4 + 2][row] = av.z;
            Asm[c4 + 3][row] = av.w;
            int gn = n0 + row + 1;
            if (gn > NN_) gn = NN_;      // clamp (store is guarded)
            float4 bv = *(const float4*)(emb + (long)gn * H_ + kc + c4);
            Bsm[c4 + 0][row] = bv.x;
            Bsm[c4 + 1][row] = bv.y;
            Bsm[c4 + 2][row] = bv.z;
            Bsm[c4 + 3][row] = bv.w;
        }
        __syncthreads();

#pragma unroll
        for (int k = 0; k < BK; k++) {
            float a[8], bb[8];
            *(float4*)&a[0]  = *(const float4*)&Asm[k][ty * 8];
            *(float4*)&a[4]  = *(const float4*)&Asm[k][ty * 8 + 4];
            *(float4*)&bb[0] = *(const float4*)&Bsm[k][tx * 8];
            *(float4*)&bb[4] = *(const float4*)&Bsm[k][tx * 8 + 4];
#pragma unroll
            for (int i = 0; i < 8; i++)
#pragma unroll
                for (int j = 0; j < 8; j++)
                    acc[i][j] += a[i] * bb[j];
        }
        __syncthreads();
    }

#pragma unroll
    for (int i = 0; i < 8; i++) {
        int m = m0 + ty * 8 + i;
        float* orow = out + (long)m * NN_ + n0 + tx * 8;
#pragma unroll
        for (int j = 0; j < 8; j++) {
            int n = n0 + tx * 8 + j;
            if (n < NN_) orow[j] = acc[i][j];
        }
    }
}

// ---------------------------------------------------------------------------
extern "C" void kernel_launch(void* const* d_in, const int* in_sizes, int n_in,
                              void* d_out, int out_size)
{
    const int*   inputs = (const int*)  d_in[0];
    const float* masks  = (const float*)d_in[1];
    const float* emb    = (const float*)d_in[2];
    const float* Qw     = (const float*)d_in[3];
    const float* Kw     = (const float*)d_in[4];
    const float* lin_w  = (const float*)d_in[5];
    const float* lin_b  = (const float*)d_in[6];

    float* out        = (float*)d_out;
    float* out_scores = out;                        // [B, N-1]
    float* out_aff    = out + (long)B_ * NN_;       // [B, L, L]

    // k1 needs ~104 KB dynamic smem
    const int smem1 = (L_*H_ + 2*L_*A_ + L_*L_ + 64 + 2*H_ + 64) * 4 + 68 * 4;
    cudaFuncSetAttribute(k1_kernel,
                         cudaFuncAttributeMaxDynamicSharedMemorySize, smem1);

    k1_kernel<<<B_, 256, smem1>>>(inputs, masks, emb, Qw, Kw, lin_w, lin_b,
                                  out_aff);

    dim3 grid2((NN_ + BN - 1) / BN, B_ / BM);
    k2_kernel<<<grid2, 256>>>(emb, out_scores);

    (void)in_sizes; (void)n_in; (void)out_size;
}

// round 10
// speedup vs baseline: 1.2501x; 1.2501x over previous
#include <cuda_runtime.h>
#include <math.h>
#include <stdint.h>

// Problem constants
#define B_   1024
#define L_   50
#define H_   256
#define N_   100000
#define A_   100
#define NN_  99999   // N-1 score columns

// Scratch: final_rep [B, H]
__device__ float g_final_rep[B_ * H_];

// ---------------------------------------------------------------------------
// mma.sync helpers (plain sm_103-legal PTX: sm_80+ features only)
// ---------------------------------------------------------------------------
__device__ __forceinline__ uint32_t f2tf32(float f) {
    uint32_t r;
    asm("cvt.rna.tf32.f32 %0, %1;" : "=r"(r) : "f"(f));
    return r;
}
__device__ __forceinline__ void mma_tf32(float* c, const uint32_t* a,
                                         const uint32_t* b) {
    asm volatile(
        "mma.sync.aligned.m16n8k8.row.col.f32.tf32.tf32.f32 "
        "{%0,%1,%2,%3}, {%4,%5,%6,%7}, {%8,%9}, {%0,%1,%2,%3};"
        : "+f"(c[0]), "+f"(c[1]), "+f"(c[2]), "+f"(c[3])
        : "r"(a[0]), "r"(a[1]), "r"(a[2]), "r"(a[3]),
          "r"(b[0]), "r"(b[1]));
}

// ---------------------------------------------------------------------------
// Kernel 1: per-batch fused pipeline (unchanged correct baseline)
// ---------------------------------------------------------------------------
__global__ void __launch_bounds__(256) k1_kernel(
    const int*   __restrict__ inputs,
    const float* __restrict__ masks,
    const float* __restrict__ emb,
    const float* __restrict__ Qw,
    const float* __restrict__ Kw,
    const float* __restrict__ lin_w,
    const float* __restrict__ lin_b,
    float*       __restrict__ out_aff)
{
    extern __shared__ float sm[];
    float* s_x     = sm;
    float* s_Q     = s_x   + L_ * H_;
    float* s_K     = s_Q   + L_ * A_;
    float* s_aff   = s_K   + L_ * A_;
    float* s_score = s_aff + L_ * L_;
    float* s_att   = s_score + 64;
    float* s_last  = s_att   + H_;
    float* s_mask  = s_last  + H_;
    int*   s_idx   = (int*)(s_mask + 64);
    int*   s_misc  = s_idx + 64;

    const int b   = blockIdx.x;
    const int tid = threadIdx.x;

    if (tid < L_) {
        s_idx[tid]  = inputs[b * L_ + tid];
        s_mask[tid] = masks[b * L_ + tid];
    }
    __syncthreads();

    for (int i = tid; i < L_ * (H_ / 4); i += 256) {
        int l = i / (H_ / 4);
        ((float4*)s_x)[i] = ((const float4*)emb)[s_idx[l] * (H_ / 4) + (i - l * (H_ / 4))];
    }
    __syncthreads();

    for (int p = tid; p < L_ * A_; p += 256) {
        int l = p / A_;
        int a = p - l * A_;
        const float4* xr = (const float4*)(s_x + l * H_);
        const float4* qr = (const float4*)(Qw + a * H_);
        const float4* kr = (const float4*)(Kw + a * H_);
        float aq = 0.f, ak = 0.f;
#pragma unroll 16
        for (int c = 0; c < H_ / 4; c++) {
            float4 x4 = xr[c], q4 = qr[c], k4 = kr[c];
            aq += x4.x * q4.x + x4.y * q4.y + x4.z * q4.z + x4.w * q4.w;
            ak += x4.x * k4.x + x4.y * k4.y + x4.z * k4.z + x4.w * k4.w;
        }
        s_Q[p] = 1.f / (1.f + expf(-aq));
        s_K[p] = 1.f / (1.f + expf(-ak));
    }
    __syncthreads();

    for (int p = tid; p < L_ * L_; p += 256) {
        int l = p / L_;
        int m = p - l * L_;
        const float4* qr = (const float4*)(s_Q + l * A_);
        const float4* kr = (const float4*)(s_K + m * A_);
        float acc = 0.f;
#pragma unroll
        for (int c = 0; c < A_ / 4; c++) {
            float4 q4 = qr[c], k4 = kr[c];
            acc += q4.x * k4.x + q4.y * k4.y + q4.z * k4.z + q4.w * k4.w;
        }
        acc *= 0.1f;
        s_aff[p] = acc;
        out_aff[(long)b * (L_ * L_) + p] = acc;
    }
    __syncthreads();

    if (tid < L_) {
        float s = 0.f;
        for (int m = 0; m < L_; m++) s += s_aff[tid * L_ + m] * s_mask[m];
        s -= s_aff[tid * L_ + tid] * s_mask[tid];
        s_score[tid] = s * s_mask[tid];
    }
    __syncthreads();

    if (tid == 0) {
        float mx = -1e30f;
        for (int l = 0; l < L_; l++) mx = fmaxf(mx, s_score[l]);
        float sum = 0.f;
        for (int l = 0; l < L_; l++) {
            float e = expf(s_score[l] - mx) * s_mask[l];
            s_aff[l] = e;
            sum += e;
        }
        float inv = 1.f / sum;
        for (int l = 0; l < L_; l++) s_score[l] = s_aff[l] * inv;
        float fl = 0.f;
        for (int m = 0; m < L_; m++) fl += s_mask[m];
        int len = (int)fl;
        s_misc[0] = s_idx[len - 1];
    }
    __syncthreads();

    const int last_id = s_misc[0];
    s_last[tid] = emb[(long)last_id * H_ + tid];
    float att = 0.f;
#pragma unroll 10
    for (int l = 0; l < L_; l++) att += s_score[l] * s_x[l * H_ + tid];
    s_att[tid] = att;
    __syncthreads();

    float acc = lin_b[tid];
    const float4* w  = (const float4*)(lin_w + tid * (2 * H_));
    const float4* a4 = (const float4*)s_att;
    const float4* l4 = (const float4*)s_last;
#pragma unroll 8
    for (int c = 0; c < H_ / 4; c++) {
        float4 wv = w[c], av = a4[c];
        acc += wv.x * av.x + wv.y * av.y + wv.z * av.z + wv.w * av.w;
    }
#pragma unroll 8
    for (int c = 0; c < H_ / 4; c++) {
        float4 wv = w[H_ / 4 + c], lv = l4[c];
        acc += wv.x * lv.x + wv.y * lv.y + wv.z * lv.z + wv.w * lv.w;
    }
    g_final_rep[b * H_ + tid] = acc;
}

// ---------------------------------------------------------------------------
// Kernel 2 (mma.sync tf32): scores[b,n] = dot(final_rep[b], emb[n+1])
//   CTA tile 128x128, K staged 32, double-buffered padded smem,
//   8 warps (2m x 4n), warp tile 64x32, m16n8k8 fragments.
// ---------------------------------------------------------------------------
#define BM  128
#define BN  128
#define BK  32
#define BKP 36     // padded row pitch (floats): fragment reads bank == lane

// dyn smem: A[2][BM][BKP] + B[2][BN][BKP] = 73728 B; epilogue reuses 66048 B
#define K2_SMEM (2 * (BM + BN) * BKP * 4)

__global__ void __launch_bounds__(256, 1) k2_mma(
    const float* __restrict__ emb,
    float*       __restrict__ out)
{
    extern __shared__ float sm2[];
    float* Abuf = sm2;                      // [2][BM][BKP]
    float* Bbuf = sm2 + 2 * BM * BKP;       // [2][BN][BKP]

    const int tid  = threadIdx.x;
    const int lane = tid & 31;
    const int wid  = tid >> 5;
    const int l4   = lane & 3;
    const int lq   = lane >> 2;
    const int wm   = (wid & 1) * 64;        // warp m offset in tile
    const int wn   = (wid >> 1) * 32;       // warp n offset in tile

    const int m0 = blockIdx.x * BM;         // 8 m-tiles, x-fastest: share B in L2
    const int n0 = blockIdx.y * BN;         // 782 n-tiles

    const int ldrow = tid >> 3;             // 0..31 -> rows row..row+96 step 32? no:
    // load mapping: v = tid + i*256, row = v>>3 (0..127), q = v&7 (float4 col)

    float c[4][4][4];
#pragma unroll
    for (int mi = 0; mi < 4; mi++)
#pragma unroll
        for (int ni = 0; ni < 4; ni++)
#pragma unroll
            for (int j = 0; j < 4; j++) c[mi][ni][j] = 0.f;

    const float* Ag = g_final_rep + (size_t)m0 * H_;

    // ---- prologue: stage 0 ----
    {
        const float* As = Ag;
        const float* Bs = emb;
#pragma unroll
        for (int i = 0; i < 4; i++) {
            int v = tid + i * 256, row = v >> 3, q = v & 7;
            float4 av = *(const float4*)(As + (size_t)row * H_ + q * 4);
            int gn = n0 + row + 1; if (gn > N_ - 1) gn = N_ - 1;
            float4 bv = *(const float4*)(Bs + (size_t)gn * H_ + q * 4);
            uint4* ad = (uint4*)(Abuf + row * BKP + q * 4);
            uint4* bd = (uint4*)(Bbuf + row * BKP + q * 4);
            *ad = make_uint4(f2tf32(av.x), f2tf32(av.y), f2tf32(av.z), f2tf32(av.w));
            *bd = make_uint4(f2tf32(bv.x), f2tf32(bv.y), f2tf32(bv.z), f2tf32(bv.w));
        }
    }
    __syncthreads();
    (void)ldrow;

#pragma unroll 1
    for (int s = 0; s < H_ / BK; s++) {          // 8 stages
        const int buf = s & 1;
        float4 ra[4], rb[4];
        if (s < H_ / BK - 1) {                   // prefetch next stage
            const float* As = Ag + (s + 1) * BK;
            const float* Bs = emb + (s + 1) * BK;
#pragma unroll
            for (int i = 0; i < 4; i++) {
                int v = tid + i * 256, row = v >> 3, q = v & 7;
                ra[i] = *(const float4*)(As + (size_t)row * H_ + q * 4);
                int gn = n0 + row + 1; if (gn > N_ - 1) gn = N_ - 1;
                rb[i] = *(const float4*)(Bs + (size_t)gn * H_ + q * 4);
            }
        }

        // ---- compute current stage ----
        const uint32_t* Au = (const uint32_t*)(Abuf + buf * BM * BKP);
        const uint32_t* Bu = (const uint32_t*)(Bbuf + buf * BN * BKP);
#pragma unroll
        for (int kk = 0; kk < 4; kk++) {
            const int kb = kk * 8;
            uint32_t a[4][4], bfr[4][2];
#pragma unroll
            for (int mi = 0; mi < 4; mi++) {
                int r = wm + mi * 16 + lq;
                a[mi][0] = Au[(r)     * BKP + kb + l4];
                a[mi][1] = Au[(r + 8) * BKP + kb + l4];
                a[mi][2] = Au[(r)     * BKP + kb + l4 + 4];
                a[mi][3] = Au[(r + 8) * BKP + kb + l4 + 4];
            }
#pragma unroll
            for (int ni = 0; ni < 4; ni++) {
                int n = wn + ni * 8 + lq;
                bfr[ni][0] = Bu[n * BKP + kb + l4];
                bfr[ni][1] = Bu[n * BKP + kb + l4 + 4];
            }
#pragma unroll
            for (int mi = 0; mi < 4; mi++)
#pragma unroll
                for (int ni = 0; ni < 4; ni++)
                    mma_tf32(c[mi][ni], a[mi], bfr[ni]);
        }

        if (s < H_ / BK - 1) {                   // store prefetched stage
            const int nb = (s + 1) & 1;
            float* Ad = Abuf + nb * BM * BKP;
            float* Bd = Bbuf + nb * BN * BKP;
#pragma unroll
            for (int i = 0; i < 4; i++) {
                int v = tid + i * 256, row = v >> 3, q = v & 7;
                uint4* ad = (uint4*)(Ad + row * BKP + q * 4);
                uint4* bd = (uint4*)(Bd + row * BKP + q * 4);
                *ad = make_uint4(f2tf32(ra[i].x), f2tf32(ra[i].y),
                                 f2tf32(ra[i].z), f2tf32(ra[i].w));
                *bd = make_uint4(f2tf32(rb[i].x), f2tf32(rb[i].y),
                                 f2tf32(rb[i].z), f2tf32(rb[i].w));
            }
            __syncthreads();
        }
    }
    __syncthreads();   // smem now reusable for epilogue

    // ---- epilogue: fragments -> padded smem -> coalesced global stores ----
    float* so = sm2;   // [128][129]
#pragma unroll
    for (int mi = 0; mi < 4; mi++) {
        int r = wm + mi * 16 + lq;
#pragma unroll
        for (int ni = 0; ni < 4; ni++) {
            int cn = wn + ni * 8 + 2 * l4;
            so[(r)     * 129 + cn]     = c[mi][ni][0];
            so[(r)     * 129 + cn + 1] = c[mi][ni][1];
            so[(r + 8) * 129 + cn]     = c[mi][ni][2];
            so[(r + 8) * 129 + cn + 1] = c[mi][ni][3];
        }
    }
    __syncthreads();

#pragma unroll 8
    for (int i = tid; i < BM * BN; i += 256) {
        int r = i >> 7, cn = i & 127;
        if (n0 + cn < NN_)
            out[(size_t)(m0 + r) * NN_ + n0 + cn] = so[r * 129 + cn];
    }
}

// ---------------------------------------------------------------------------
extern "C" void kernel_launch(void* const* d_in, const int* in_sizes, int n_in,
                              void* d_out, int out_size)
{
    const int*   inputs = (const int*)  d_in[0];
    const float* masks  = (const float*)d_in[1];
    const float* emb    = (const float*)d_in[2];
    const float* Qw     = (const float*)d_in[3];
    const float* Kw     = (const float*)d_in[4];
    const float* lin_w  = (const float*)d_in[5];
    const float* lin_b  = (const float*)d_in[6];

    float* out        = (float*)d_out;
    float* out_scores = out;                   // [B, N-1]
    float* out_aff    = out + (long)B_ * NN_;  // [B, L, L]

    const int smem1 = (L_*H_ + 2*L_*A_ + L_*L_ + 64 + 2*H_ + 64) * 4 + 68 * 4;
    cudaFuncSetAttribute(k1_kernel,
                         cudaFuncAttributeMaxDynamicSharedMemorySize, smem1);
    k1_kernel<<<B_, 256, smem1>>>(inputs, masks, emb, Qw, Kw, lin_w, lin_b,
                                  out_aff);

    cudaFuncSetAttribute(k2_mma,
                         cudaFuncAttributeMaxDynamicSharedMemorySize, K2_SMEM);
    dim3 grid2(B_ / BM, (NN_ + BN - 1) / BN);   // (8, 782)
    k2_mma<<<grid2, 256, K2_SMEM>>>(emb, out_scores);

    (void)in_sizes; (void)n_in; (void)out_size;
}

// round 11
// speedup vs baseline: 6.7176x; 5.3738x over previous
#include <cuda_runtime.h>
#include <math.h>
#include <stdint.h>

// Problem constants
#define B_   1024
#define L_   50
#define H_   256
#define N_   100000
#define A_   100
#define NN_  99999   // N-1 score columns
#define BL_  (B_ * L_)   // 51200 rows
#define QKN  200         // Q|K concat width

// Scratch (device globals: no runtime allocation allowed)
__device__ float g_final_rep[B_ * H_];            // 1 MB
__device__ float g_qk[(size_t)BL_ * QKN];         // 41 MB: [row, 0..99]=Q, [100..199]=K

// ---------------------------------------------------------------------------
// mma.sync helpers (plain sm_103-legal PTX)
// ---------------------------------------------------------------------------
__device__ __forceinline__ uint32_t f2tf32(float f) {
    uint32_t r;
    asm("cvt.rna.tf32.f32 %0, %1;" : "=r"(r) : "f"(f));
    return r;
}
__device__ __forceinline__ void mma_tf32(float* c, const uint32_t* a,
                                         const uint32_t* b) {
    asm volatile(
        "mma.sync.aligned.m16n8k8.row.col.f32.tf32.tf32.f32 "
        "{%0,%1,%2,%3}, {%4,%5,%6,%7}, {%8,%9}, {%0,%1,%2,%3};"
        : "+f"(c[0]), "+f"(c[1]), "+f"(c[2]), "+f"(c[3])
        : "r"(a[0]), "r"(a[1]), "r"(a[2]), "r"(a[3]),
          "r"(b[0]), "r"(b[1]));
}

#define BM  128
#define BN  128
#define BK  32
#define BKP 36
#define GEMM_SMEM (2 * (BM + BN) * BKP * 4)        // 73728
#define K1A_SMEM  (GEMM_SMEM + 512)                // + ids cache

// ---------------------------------------------------------------------------
// k1a: QK = sigmoid( X @ [Qw;Kw]^T ),  X rows gathered via inputs -> emb
//   M = 51200 (400 m-tiles), N = 200 (2 n-tiles), K = 256
// ---------------------------------------------------------------------------
__global__ void __launch_bounds__(256, 1) k1a_mma(
    const int*   __restrict__ inputs,
    const float* __restrict__ emb,
    const float* __restrict__ Qw,
    const float* __restrict__ Kw)
{
    extern __shared__ float sm2[];
    float* Abuf = sm2;                      // [2][BM][BKP]
    float* Bbuf = sm2 + 2 * BM * BKP;       // [2][BN][BKP]
    int*   s_ids = (int*)(sm2 + 2 * (BM + BN) * BKP);

    const int tid  = threadIdx.x;
    const int lane = tid & 31;
    const int wid  = tid >> 5;
    const int l4   = lane & 3;
    const int lq   = lane >> 2;
    const int wm   = (wid & 1) * 64;
    const int wn   = (wid >> 1) * 32;

    const int m0 = blockIdx.x * BM;
    const int n0 = blockIdx.y * BN;

    if (tid < 128) s_ids[tid] = inputs[m0 + tid];
    __syncthreads();

    float c[4][4][4];
#pragma unroll
    for (int mi = 0; mi < 4; mi++)
#pragma unroll
        for (int ni = 0; ni < 4; ni++)
#pragma unroll
            for (int j = 0; j < 4; j++) c[mi][ni][j] = 0.f;

    // prologue: stage 0
    {
#pragma unroll
        for (int i = 0; i < 4; i++) {
            int v = tid + i * 256, row = v >> 3, q = v & 7;
            float4 av = *(const float4*)(emb + (size_t)s_ids[row] * H_ + q * 4);
            int gb = n0 + row; if (gb > QKN - 1) gb = QKN - 1;
            const float* brow = (gb < A_) ? (Qw + (size_t)gb * H_)
                                          : (Kw + (size_t)(gb - A_) * H_);
            float4 bv = *(const float4*)(brow + q * 4);
            *(uint4*)(Abuf + row * BKP + q * 4) =
                make_uint4(f2tf32(av.x), f2tf32(av.y), f2tf32(av.z), f2tf32(av.w));
            *(uint4*)(Bbuf + row * BKP + q * 4) =
                make_uint4(f2tf32(bv.x), f2tf32(bv.y), f2tf32(bv.z), f2tf32(bv.w));
        }
    }
    __syncthreads();

#pragma unroll 1
    for (int s = 0; s < H_ / BK; s++) {
        const int buf = s & 1;
        float4 ra[4], rb[4];
        if (s < H_ / BK - 1) {
            const int ko = (s + 1) * BK;
#pragma unroll
            for (int i = 0; i < 4; i++) {
                int v = tid + i * 256, row = v >> 3, q = v & 7;
                ra[i] = *(const float4*)(emb + (size_t)s_ids[row] * H_ + ko + q * 4);
                int gb = n0 + row; if (gb > QKN - 1) gb = QKN - 1;
                const float* brow = (gb < A_) ? (Qw + (size_t)gb * H_)
                                              : (Kw + (size_t)(gb - A_) * H_);
                rb[i] = *(const float4*)(brow + ko + q * 4);
            }
        }

        const uint32_t* Au = (const uint32_t*)(Abuf + buf * BM * BKP);
        const uint32_t* Bu = (const uint32_t*)(Bbuf + buf * BN * BKP);
#pragma unroll
        for (int kk = 0; kk < 4; kk++) {
            const int kb = kk * 8;
            uint32_t a[4][4], bfr[4][2];
#pragma unroll
            for (int mi = 0; mi < 4; mi++) {
                int r = wm + mi * 16 + lq;
                a[mi][0] = Au[(r)     * BKP + kb + l4];
                a[mi][1] = Au[(r + 8) * BKP + kb + l4];
                a[mi][2] = Au[(r)     * BKP + kb + l4 + 4];
                a[mi][3] = Au[(r + 8) * BKP + kb + l4 + 4];
            }
#pragma unroll
            for (int ni = 0; ni < 4; ni++) {
                int n = wn + ni * 8 + lq;
                bfr[ni][0] = Bu[n * BKP + kb + l4];
                bfr[ni][1] = Bu[n * BKP + kb + l4 + 4];
            }
#pragma unroll
            for (int mi = 0; mi < 4; mi++)
#pragma unroll
                for (int ni = 0; ni < 4; ni++)
                    mma_tf32(c[mi][ni], a[mi], bfr[ni]);
        }

        if (s < H_ / BK - 1) {
            const int nb = (s + 1) & 1;
            float* Ad = Abuf + nb * BM * BKP;
            float* Bd = Bbuf + nb * BN * BKP;
#pragma unroll
            for (int i = 0; i < 4; i++) {
                int v = tid + i * 256, row = v >> 3, q = v & 7;
                *(uint4*)(Ad + row * BKP + q * 4) =
                    make_uint4(f2tf32(ra[i].x), f2tf32(ra[i].y),
                               f2tf32(ra[i].z), f2tf32(ra[i].w));
                *(uint4*)(Bd + row * BKP + q * 4) =
                    make_uint4(f2tf32(rb[i].x), f2tf32(rb[i].y),
                               f2tf32(rb[i].z), f2tf32(rb[i].w));
            }
            __syncthreads();
        }
    }
    __syncthreads();

    // epilogue: fragments -> smem -> sigmoid -> g_qk
    float* so = sm2;   // [128][129]
#pragma unroll
    for (int mi = 0; mi < 4; mi++) {
        int r = wm + mi * 16 + lq;
#pragma unroll
        for (int ni = 0; ni < 4; ni++) {
            int cn = wn + ni * 8 + 2 * l4;
            so[(r)     * 129 + cn]     = c[mi][ni][0];
            so[(r)     * 129 + cn + 1] = c[mi][ni][1];
            so[(r + 8) * 129 + cn]     = c[mi][ni][2];
            so[(r + 8) * 129 + cn + 1] = c[mi][ni][3];
        }
    }
    __syncthreads();

#pragma unroll 8
    for (int i = tid; i < BM * BN; i += 256) {
        int r = i >> 7, cn = i & 127;
        int col = n0 + cn;
        if (col < QKN)
            g_qk[(size_t)(m0 + r) * QKN + col] =
                1.f / (1.f + expf(-so[r * 129 + cn]));
    }
}

// ---------------------------------------------------------------------------
// k1b: per-batch affinity + softmax + att + final_rep (Q/K from g_qk)
// ---------------------------------------------------------------------------
__global__ void __launch_bounds__(256) k1b_kernel(
    const int*   __restrict__ inputs,
    const float* __restrict__ masks,
    const float* __restrict__ emb,
    const float* __restrict__ lin_w,
    const float* __restrict__ lin_b,
    float*       __restrict__ out_aff)
{
    extern __shared__ float sm[];
    float* s_Q     = sm;                   // 5000
    float* s_K     = s_Q + L_ * A_;        // 5000
    float* s_aff   = s_K + L_ * A_;        // 2500
    float* s_score = s_aff + L_ * L_;      // 64
    float* s_att   = s_score + 64;         // 256
    float* s_last  = s_att + H_;           // 256
    float* s_mask  = s_last + H_;          // 64
    int*   s_idx   = (int*)(s_mask + 64);  // 64
    int*   s_misc  = s_idx + 64;           // 16

    const int b   = blockIdx.x;
    const int tid = threadIdx.x;

    if (tid < L_) {
        s_idx[tid]  = inputs[b * L_ + tid];
        s_mask[tid] = masks[b * L_ + tid];
    }

    // load Q|K rows for this batch (coalesced float4)
    const float4* qrow = (const float4*)(g_qk + (size_t)b * L_ * QKN);
    for (int v = tid; v < L_ * (QKN / 4); v += 256) {   // 2500 float4
        int l = v / (QKN / 4);
        int j = v - l * (QKN / 4);
        float4 t = qrow[v];
        if (j < A_ / 4) ((float4*)(s_Q + l * A_))[j] = t;
        else            ((float4*)(s_K + l * A_))[j - A_ / 4] = t;
    }
    __syncthreads();

    // affinity[l,m] = dot(Q[l],K[m]) / 10  (full) -> output #2
    for (int p = tid; p < L_ * L_; p += 256) {
        int l = p / L_;
        int m = p - l * L_;
        const float4* qr = (const float4*)(s_Q + l * A_);
        const float4* kr = (const float4*)(s_K + m * A_);
        float acc = 0.f;
#pragma unroll
        for (int c = 0; c < A_ / 4; c++) {
            float4 q4 = qr[c], k4 = kr[c];
            acc += q4.x * k4.x + q4.y * k4.y + q4.z * k4.z + q4.w * k4.w;
        }
        acc *= 0.1f;
        s_aff[p] = acc;
        out_aff[(size_t)b * (L_ * L_) + p] = acc;
    }
    __syncthreads();

    if (tid < L_) {
        float s = 0.f;
        for (int m = 0; m < L_; m++) s += s_aff[tid * L_ + m] * s_mask[m];
        s -= s_aff[tid * L_ + tid] * s_mask[tid];
        s_score[tid] = s * s_mask[tid];
    }
    __syncthreads();

    if (tid == 0) {
        float mx = -1e30f;
        for (int l = 0; l < L_; l++) mx = fmaxf(mx, s_score[l]);
        float sum = 0.f;
        for (int l = 0; l < L_; l++) {
            float e = expf(s_score[l] - mx) * s_mask[l];
            s_aff[l] = e;
            sum += e;
        }
        float inv = 1.f / sum;
        for (int l = 0; l < L_; l++) s_score[l] = s_aff[l] * inv;
        float fl = 0.f;
        for (int m = 0; m < L_; m++) fl += s_mask[m];
        s_misc[0] = s_idx[(int)fl - 1];
    }
    __syncthreads();

    // att via direct emb gather (coalesced over h = tid)
    const int last_id = s_misc[0];
    s_last[tid] = emb[(size_t)last_id * H_ + tid];
    float att = 0.f;
#pragma unroll 10
    for (int l = 0; l < L_; l++)
        att += s_score[l] * emb[(size_t)s_idx[l] * H_ + tid];
    s_att[tid] = att;
    __syncthreads();

    float acc = lin_b[tid];
    const float4* w  = (const float4*)(lin_w + tid * (2 * H_));
    const float4* a4 = (const float4*)s_att;
    const float4* l4 = (const float4*)s_last;
#pragma unroll 8
    for (int c = 0; c < H_ / 4; c++) {
        float4 wv = w[c], av = a4[c];
        acc += wv.x * av.x + wv.y * av.y + wv.z * av.z + wv.w * av.w;
    }
#pragma unroll 8
    for (int c = 0; c < H_ / 4; c++) {
        float4 wv = w[H_ / 4 + c], lv = l4[c];
        acc += wv.x * lv.x + wv.y * lv.y + wv.z * lv.z + wv.w * lv.w;
    }
    g_final_rep[b * H_ + tid] = acc;
}

// ---------------------------------------------------------------------------
// k2 (unchanged, proven): scores = final_rep @ emb[1:]^T  via mma.sync tf32
// ---------------------------------------------------------------------------
__global__ void __launch_bounds__(256, 1) k2_mma(
    const float* __restrict__ emb,
    float*       __restrict__ out)
{
    extern __shared__ float sm2[];
    float* Abuf = sm2;
    float* Bbuf = sm2 + 2 * BM * BKP;

    const int tid  = threadIdx.x;
    const int lane = tid & 31;
    const int wid  = tid >> 5;
    const int l4   = lane & 3;
    const int lq   = lane >> 2;
    const int wm   = (wid & 1) * 64;
    const int wn   = (wid >> 1) * 32;

    const int m0 = blockIdx.x * BM;
    const int n0 = blockIdx.y * BN;

    float c[4][4][4];
#pragma unroll
    for (int mi = 0; mi < 4; mi++)
#pragma unroll
        for (int ni = 0; ni < 4; ni++)
#pragma unroll
            for (int j = 0; j < 4; j++) c[mi][ni][j] = 0.f;

    const float* Ag = g_final_rep + (size_t)m0 * H_;

    {
#pragma unroll
        for (int i = 0; i < 4; i++) {
            int v = tid + i * 256, row = v >> 3, q = v & 7;
            float4 av = *(const float4*)(Ag + (size_t)row * H_ + q * 4);
            int gn = n0 + row + 1; if (gn > N_ - 1) gn = N_ - 1;
            float4 bv = *(const float4*)(emb + (size_t)gn * H_ + q * 4);
            *(uint4*)(Abuf + row * BKP + q * 4) =
                make_uint4(f2tf32(av.x), f2tf32(av.y), f2tf32(av.z), f2tf32(av.w));
            *(uint4*)(Bbuf + row * BKP + q * 4) =
                make_uint4(f2tf32(bv.x), f2tf32(bv.y), f2tf32(bv.z), f2tf32(bv.w));
        }
    }
    __syncthreads();

#pragma unroll 1
    for (int s = 0; s < H_ / BK; s++) {
        const int buf = s & 1;
        float4 ra[4], rb[4];
        if (s < H_ / BK - 1) {
            const int ko = (s + 1) * BK;
#pragma unroll
            for (int i = 0; i < 4; i++) {
                int v = tid + i * 256, row = v >> 3, q = v & 7;
                ra[i] = *(const float4*)(Ag + (size_t)row * H_ + ko + q * 4);
                int gn = n0 + row + 1; if (gn > N_ - 1) gn = N_ - 1;
                rb[i] = *(const float4*)(emb + (size_t)gn * H_ + ko + q * 4);
            }
        }

        const uint32_t* Au = (const uint32_t*)(Abuf + buf * BM * BKP);
        const uint32_t* Bu = (const uint32_t*)(Bbuf + buf * BN * BKP);
#pragma unroll
        for (int kk = 0; kk < 4; kk++) {
            const int kb = kk * 8;
            uint32_t a[4][4], bfr[4][2];
#pragma unroll
            for (int mi = 0; mi < 4; mi++) {
                int r = wm + mi * 16 + lq;
                a[mi][0] = Au[(r)     * BKP + kb + l4];
                a[mi][1] = Au[(r + 8) * BKP + kb + l4];
                a[mi][2] = Au[(r)     * BKP + kb + l4 + 4];
                a[mi][3] = Au[(r + 8) * BKP + kb + l4 + 4];
            }
#pragma unroll
            for (int ni = 0; ni < 4; ni++) {
                int n = wn + ni * 8 + lq;
                bfr[ni][0] = Bu[n * BKP + kb + l4];
                bfr[ni][1] = Bu[n * BKP + kb + l4 + 4];
            }
#pragma unroll
            for (int mi = 0; mi < 4; mi++)
#pragma unroll
                for (int ni = 0; ni < 4; ni++)
                    mma_tf32(c[mi][ni], a[mi], bfr[ni]);
        }

        if (s < H_ / BK - 1) {
            const int nb = (s + 1) & 1;
            float* Ad = Abuf + nb * BM * BKP;
            float* Bd = Bbuf + nb * BN * BKP;
#pragma unroll
            for (int i = 0; i < 4; i++) {
                int v = tid + i * 256, row = v >> 3, q = v & 7;
                *(uint4*)(Ad + row * BKP + q * 4) =
                    make_uint4(f2tf32(ra[i].x), f2tf32(ra[i].y),
                               f2tf32(ra[i].z), f2tf32(ra[i].w));
                *(uint4*)(Bd + row * BKP + q * 4) =
                    make_uint4(f2tf32(rb[i].x), f2tf32(rb[i].y),
                               f2tf32(rb[i].z), f2tf32(rb[i].w));
            }
            __syncthreads();
        }
    }
    __syncthreads();

    float* so = sm2;   // [128][129]
#pragma unroll
    for (int mi = 0; mi < 4; mi++) {
        int r = wm + mi * 16 + lq;
#pragma unroll
        for (int ni = 0; ni < 4; ni++) {
            int cn = wn + ni * 8 + 2 * l4;
            so[(r)     * 129 + cn]     = c[mi][ni][0];
            so[(r)     * 129 + cn + 1] = c[mi][ni][1];
            so[(r + 8) * 129 + cn]     = c[mi][ni][2];
            so[(r + 8) * 129 + cn + 1] = c[mi][ni][3];
        }
    }
    __syncthreads();

#pragma unroll 8
    for (int i = tid; i < BM * BN; i += 256) {
        int r = i >> 7, cn = i & 127;
        if (n0 + cn < NN_)
            out[(size_t)(m0 + r) * NN_ + n0 + cn] = so[r * 129 + cn];
    }
}

// ---------------------------------------------------------------------------
extern "C" void kernel_launch(void* const* d_in, const int* in_sizes, int n_in,
                              void* d_out, int out_size)
{
    const int*   inputs = (const int*)  d_in[0];
    const float* masks  = (const float*)d_in[1];
    const float* emb    = (const float*)d_in[2];
    const float* Qw     = (const float*)d_in[3];
    const float* Kw     = (const float*)d_in[4];
    const float* lin_w  = (const float*)d_in[5];
    const float* lin_b  = (const float*)d_in[6];

    float* out        = (float*)d_out;
    float* out_scores = out;                   // [B, N-1]
    float* out_aff    = out + (size_t)B_ * NN_;  // [B, L, L]

    cudaFuncSetAttribute(k1a_mma,
                         cudaFuncAttributeMaxDynamicSharedMemorySize, K1A_SMEM);
    dim3 g1a(BL_ / BM, (QKN + BN - 1) / BN);   // (400, 2)
    k1a_mma<<<g1a, 256, K1A_SMEM>>>(inputs, emb, Qw, Kw);

    const int smem1b = (L_*A_*2 + L_*L_ + 64 + 2*H_ + 64 + 64 + 16) * 4;
    cudaFuncSetAttribute(k1b_kernel,
                         cudaFuncAttributeMaxDynamicSharedMemorySize, smem1b);
    k1b_kernel<<<B_, 256, smem1b>>>(inputs, masks, emb, lin_w, lin_b, out_aff);

    cudaFuncSetAttribute(k2_mma,
                         cudaFuncAttributeMaxDynamicSharedMemorySize, GEMM_SMEM);
    dim3 g2(B_ / BM, (NN_ + BN - 1) / BN);     // (8, 782)
    k2_mma<<<g2, 256, GEMM_SMEM>>>(emb, out_scores);

    (void)in_sizes; (void)n_in; (void)out_size;
}

// round 12
// speedup vs baseline: 8.7515x; 1.3028x over previous
#include <cuda_runtime.h>
#include <math.h>
#include <stdint.h>

// Problem constants
#define B_   1024
#define L_   50
#define H_   256
#define N_   100000
#define A_   100
#define NN_  99999
#define BL_  (B_ * L_)   // 51200
#define QKN  200         // Q|K concat width

// Scratch (device globals — no runtime allocation allowed)
__device__ float g_final_rep[B_ * H_];            // 1 MB (tf32-rounded bits)
__device__ float g_qk[(size_t)BL_ * QKN];         // 41 MB
__device__ float g_cat[B_ * 2 * H_];              // 2 MB  [att|last]
__device__ float g_embt[(size_t)N_ * H_];         // 102 MB (tf32-rounded emb)

// ---------------------------------------------------------------------------
// helpers
// ---------------------------------------------------------------------------
__device__ __forceinline__ uint32_t f2tf32(float f) {
    uint32_t r;
    asm("cvt.rna.tf32.f32 %0, %1;" : "=r"(r) : "f"(f));
    return r;
}
__device__ __forceinline__ void mma_tf32(float* c, const uint32_t* a,
                                         const uint32_t* b) {
    asm volatile(
        "mma.sync.aligned.m16n8k8.row.col.f32.tf32.tf32.f32 "
        "{%0,%1,%2,%3}, {%4,%5,%6,%7}, {%8,%9}, {%0,%1,%2,%3};"
        : "+f"(c[0]), "+f"(c[1]), "+f"(c[2]), "+f"(c[3])
        : "r"(a[0]), "r"(a[1]), "r"(a[2]), "r"(a[3]),
          "r"(b[0]), "r"(b[1]));
}
__device__ __forceinline__ uint32_t smem_u32(const void* p) {
    uint32_t a;
    asm("{ .reg .u64 t; cvta.to.shared.u64 t, %1; cvt.u32.u64 %0, t; }"
        : "=r"(a) : "l"(p));
    return a;
}
__device__ __forceinline__ void cpasync16(uint32_t dst, const void* src) {
    asm volatile("cp.async.cg.shared.global [%0], [%1], 16;"
                 :: "r"(dst), "l"(src));
}
__device__ __forceinline__ void cp_commit() {
    asm volatile("cp.async.commit_group;" ::: "memory");
}

#define BM  128
#define BN  128
#define BK  32
#define BKP 36
#define GEMM_SMEM (2 * (BM + BN) * BKP * 4)        // 73728
#define K1A_SMEM  (GEMM_SMEM + 512)

// ---------------------------------------------------------------------------
// k0: emb -> g_embt (tf32-rounded bits), vectorized
// ---------------------------------------------------------------------------
__global__ void __launch_bounds__(256) k0_cvt(const float* __restrict__ emb)
{
    size_t i = (size_t)blockIdx.x * 256 + threadIdx.x;   // float4 index
    float4 v = ((const float4*)emb)[i];
    ((uint4*)g_embt)[i] = make_uint4(f2tf32(v.x), f2tf32(v.y),
                                     f2tf32(v.z), f2tf32(v.w));
}

// ---------------------------------------------------------------------------
// k1a: QK = sigmoid( X @ [Qw;Kw]^T ), X gathered via inputs->emb (unchanged)
// ---------------------------------------------------------------------------
__global__ void __launch_bounds__(256, 1) k1a_mma(
    const int*   __restrict__ inputs,
    const float* __restrict__ emb,
    const float* __restrict__ Qw,
    const float* __restrict__ Kw)
{
    extern __shared__ float sm2[];
    float* Abuf = sm2;
    float* Bbuf = sm2 + 2 * BM * BKP;
    int*   s_ids = (int*)(sm2 + 2 * (BM + BN) * BKP);

    const int tid  = threadIdx.x;
    const int lane = tid & 31;
    const int wid  = tid >> 5;
    const int l4   = lane & 3;
    const int lq   = lane >> 2;
    const int wm   = (wid & 1) * 64;
    const int wn   = (wid >> 1) * 32;

    const int m0 = blockIdx.x * BM;
    const int n0 = blockIdx.y * BN;

    if (tid < 128) s_ids[tid] = inputs[m0 + tid];
    __syncthreads();

    float c[4][4][4];
#pragma unroll
    for (int mi = 0; mi < 4; mi++)
#pragma unroll
        for (int ni = 0; ni < 4; ni++)
#pragma unroll
            for (int j = 0; j < 4; j++) c[mi][ni][j] = 0.f;

    {
#pragma unroll
        for (int i = 0; i < 4; i++) {
            int v = tid + i * 256, row = v >> 3, q = v & 7;
            float4 av = *(const float4*)(emb + (size_t)s_ids[row] * H_ + q * 4);
            int gb = n0 + row; if (gb > QKN - 1) gb = QKN - 1;
            const float* brow = (gb < A_) ? (Qw + (size_t)gb * H_)
                                          : (Kw + (size_t)(gb - A_) * H_);
            float4 bv = *(const float4*)(brow + q * 4);
            *(uint4*)(Abuf + row * BKP + q * 4) =
                make_uint4(f2tf32(av.x), f2tf32(av.y), f2tf32(av.z), f2tf32(av.w));
            *(uint4*)(Bbuf + row * BKP + q * 4) =
                make_uint4(f2tf32(bv.x), f2tf32(bv.y), f2tf32(bv.z), f2tf32(bv.w));
        }
    }
    __syncthreads();

#pragma unroll 1
    for (int s = 0; s < H_ / BK; s++) {
        const int buf = s & 1;
        float4 ra[4], rb[4];
        if (s < H_ / BK - 1) {
            const int ko = (s + 1) * BK;
#pragma unroll
            for (int i = 0; i < 4; i++) {
                int v = tid + i * 256, row = v >> 3, q = v & 7;
                ra[i] = *(const float4*)(emb + (size_t)s_ids[row] * H_ + ko + q * 4);
                int gb = n0 + row; if (gb > QKN - 1) gb = QKN - 1;
                const float* brow = (gb < A_) ? (Qw + (size_t)gb * H_)
                                              : (Kw + (size_t)(gb - A_) * H_);
                rb[i] = *(const float4*)(brow + ko + q * 4);
            }
        }

        const uint32_t* Au = (const uint32_t*)(Abuf + buf * BM * BKP);
        const uint32_t* Bu = (const uint32_t*)(Bbuf + buf * BN * BKP);
#pragma unroll
        for (int kk = 0; kk < 4; kk++) {
            const int kb = kk * 8;
            uint32_t a[4][4], bfr[4][2];
#pragma unroll
            for (int mi = 0; mi < 4; mi++) {
                int r = wm + mi * 16 + lq;
                a[mi][0] = Au[(r)     * BKP + kb + l4];
                a[mi][1] = Au[(r + 8) * BKP + kb + l4];
                a[mi][2] = Au[(r)     * BKP + kb + l4 + 4];
                a[mi][3] = Au[(r + 8) * BKP + kb + l4 + 4];
            }
#pragma unroll
            for (int ni = 0; ni < 4; ni++) {
                int n = wn + ni * 8 + lq;
                bfr[ni][0] = Bu[n * BKP + kb + l4];
                bfr[ni][1] = Bu[n * BKP + kb + l4 + 4];
            }
#pragma unroll
            for (int mi = 0; mi < 4; mi++)
#pragma unroll
                for (int ni = 0; ni < 4; ni++)
                    mma_tf32(c[mi][ni], a[mi], bfr[ni]);
        }

        if (s < H_ / BK - 1) {
            const int nb = (s + 1) & 1;
            float* Ad = Abuf + nb * BM * BKP;
            float* Bd = Bbuf + nb * BN * BKP;
#pragma unroll
            for (int i = 0; i < 4; i++) {
                int v = tid + i * 256, row = v >> 3, q = v & 7;
                *(uint4*)(Ad + row * BKP + q * 4) =
                    make_uint4(f2tf32(ra[i].x), f2tf32(ra[i].y),
                               f2tf32(ra[i].z), f2tf32(ra[i].w));
                *(uint4*)(Bd + row * BKP + q * 4) =
                    make_uint4(f2tf32(rb[i].x), f2tf32(rb[i].y),
                               f2tf32(rb[i].z), f2tf32(rb[i].w));
            }
            __syncthreads();
        }
    }
    __syncthreads();

    float* so = sm2;   // [128][129]
#pragma unroll
    for (int mi = 0; mi < 4; mi++) {
        int r = wm + mi * 16 + lq;
#pragma unroll
        for (int ni = 0; ni < 4; ni++) {
            int cn = wn + ni * 8 + 2 * l4;
            so[(r)     * 129 + cn]     = c[mi][ni][0];
            so[(r)     * 129 + cn + 1] = c[mi][ni][1];
            so[(r + 8) * 129 + cn]     = c[mi][ni][2];
            so[(r + 8) * 129 + cn + 1] = c[mi][ni][3];
        }
    }
    __syncthreads();

#pragma unroll 8
    for (int i = tid; i < BM * BN; i += 256) {
        int r = i >> 7, cn = i & 127;
        int col = n0 + cn;
        if (col < QKN)
            g_qk[(size_t)(m0 + r) * QKN + col] =
                1.f / (1.f + expf(-so[r * 129 + cn]));
    }
}

// ---------------------------------------------------------------------------
// k1b: per-batch affinity + softmax + att; writes cat=[att|last] to g_cat
// ---------------------------------------------------------------------------
__global__ void __launch_bounds__(256) k1b_kernel(
    const int*   __restrict__ inputs,
    const float* __restrict__ masks,
    const float* __restrict__ emb,
    float*       __restrict__ out_aff)
{
    extern __shared__ float sm[];
    float* s_Q     = sm;                   // 5000
    float* s_K     = s_Q + L_ * A_;        // 5000
    float* s_aff   = s_K + L_ * A_;        // 2500
    float* s_score = s_aff + L_ * L_;      // 64
    float* s_mask  = s_score + 64;         // 64
    int*   s_idx   = (int*)(s_mask + 64);  // 64
    int*   s_misc  = s_idx + 64;           // 16

    const int b   = blockIdx.x;
    const int tid = threadIdx.x;

    if (tid < L_) {
        s_idx[tid]  = inputs[b * L_ + tid];
        s_mask[tid] = masks[b * L_ + tid];
    }

    const float4* qrow = (const float4*)(g_qk + (size_t)b * L_ * QKN);
    for (int v = tid; v < L_ * (QKN / 4); v += 256) {
        int l = v / (QKN / 4);
        int j = v - l * (QKN / 4);
        float4 t = qrow[v];
        if (j < A_ / 4) ((float4*)(s_Q + l * A_))[j] = t;
        else            ((float4*)(s_K + l * A_))[j - A_ / 4] = t;
    }
    __syncthreads();

    for (int p = tid; p < L_ * L_; p += 256) {
        int l = p / L_;
        int m = p - l * L_;
        const float4* qr = (const float4*)(s_Q + l * A_);
        const float4* kr = (const float4*)(s_K + m * A_);
        float acc = 0.f;
#pragma unroll
        for (int c = 0; c < A_ / 4; c++) {
            float4 q4 = qr[c], k4 = kr[c];
            acc += q4.x * k4.x + q4.y * k4.y + q4.z * k4.z + q4.w * k4.w;
        }
        acc *= 0.1f;
        s_aff[p] = acc;
        out_aff[(size_t)b * (L_ * L_) + p] = acc;
    }
    __syncthreads();

    if (tid < L_) {
        float s = 0.f;
        for (int m = 0; m < L_; m++) s += s_aff[tid * L_ + m] * s_mask[m];
        s -= s_aff[tid * L_ + tid] * s_mask[tid];
        s_score[tid] = s * s_mask[tid];
    }
    __syncthreads();

    if (tid == 0) {
        float mx = -1e30f;
        for (int l = 0; l < L_; l++) mx = fmaxf(mx, s_score[l]);
        float sum = 0.f;
        for (int l = 0; l < L_; l++) {
            float e = expf(s_score[l] - mx) * s_mask[l];
            s_aff[l] = e;
            sum += e;
        }
        float inv = 1.f / sum;
        for (int l = 0; l < L_; l++) s_score[l] = s_aff[l] * inv;
        float fl = 0.f;
        for (int m = 0; m < L_; m++) fl += s_mask[m];
        s_misc[0] = s_idx[(int)fl - 1];
    }
    __syncthreads();

    const int last_id = s_misc[0];
    float lastv = emb[(size_t)last_id * H_ + tid];
    float att = 0.f;
#pragma unroll 10
    for (int l = 0; l < L_; l++)
        att += s_score[l] * emb[(size_t)s_idx[l] * H_ + tid];

    g_cat[(size_t)b * (2 * H_) + tid]      = att;
    g_cat[(size_t)b * (2 * H_) + H_ + tid] = lastv;
}

// ---------------------------------------------------------------------------
// k1c: final_rep = cat @ lin_w^T + lin_b  (fp32 exact; lin_w amortized x8)
//   128 CTAs x 256 threads; thread h handles output col h for 8 batches.
// ---------------------------------------------------------------------------
__global__ void __launch_bounds__(256) k1c_kernel(
    const float* __restrict__ lin_w,
    const float* __restrict__ lin_b)
{
    __shared__ float s_cat[8 * 2 * H_];    // 16 KB
    const int b0  = blockIdx.x * 8;
    const int tid = threadIdx.x;

    for (int v = tid; v < 8 * (2 * H_ / 4); v += 256)
        ((float4*)s_cat)[v] = ((const float4*)(g_cat + (size_t)b0 * 2 * H_))[v];
    __syncthreads();

    const float bias = lin_b[tid];
    float acc[8];
#pragma unroll
    for (int bb = 0; bb < 8; bb++) acc[bb] = bias;

    const float4* wrow = (const float4*)(lin_w + (size_t)tid * (2 * H_));
#pragma unroll 4
    for (int kc = 0; kc < 2 * H_ / 4; kc += 4) {
        float4 w0 = wrow[kc], w1 = wrow[kc + 1], w2 = wrow[kc + 2], w3 = wrow[kc + 3];
#pragma unroll
        for (int bb = 0; bb < 8; bb++) {
            const float4* cr = (const float4*)(s_cat + bb * 2 * H_) + kc;
            float4 c0 = cr[0], c1 = cr[1], c2 = cr[2], c3 = cr[3];
            acc[bb] += w0.x * c0.x + w0.y * c0.y + w0.z * c0.z + w0.w * c0.w
                     + w1.x * c1.x + w1.y * c1.y + w1.z * c1.z + w1.w * c1.w
                     + w2.x * c2.x + w2.y * c2.y + w2.z * c2.z + w2.w * c2.w
                     + w3.x * c3.x + w3.y * c3.y + w3.z * c3.z + w3.w * c3.w;
        }
    }
#pragma unroll
    for (int bb = 0; bb < 8; bb++)
        g_final_rep[(size_t)(b0 + bb) * H_ + tid] =
            __uint_as_float(f2tf32(acc[bb]));
}

// ---------------------------------------------------------------------------
// k2: scores = final_rep @ embt[1:]^T.  cp.async double-buffer, no cvt,
//     2 CTAs/SM.  Inputs already tf32-rounded.
// ---------------------------------------------------------------------------
__global__ void __launch_bounds__(256, 2) k2_mma(float* __restrict__ out)
{
    extern __shared__ float sm2[];
    float* Abuf = sm2;                      // [2][BM][BKP]
    float* Bbuf = sm2 + 2 * BM * BKP;       // [2][BN][BKP]
    const uint32_t sA = smem_u32(Abuf);
    const uint32_t sB = smem_u32(Bbuf);

    const int tid  = threadIdx.x;
    const int lane = tid & 31;
    const int wid  = tid >> 5;
    const int l4   = lane & 3;
    const int lq   = lane >> 2;
    const int wm   = (wid & 1) * 64;
    const int wn   = (wid >> 1) * 32;

    const int m0 = blockIdx.x * BM;
    const int n0 = blockIdx.y * BN;

    float c[4][4][4];
#pragma unroll
    for (int mi = 0; mi < 4; mi++)
#pragma unroll
        for (int ni = 0; ni < 4; ni++)
#pragma unroll
            for (int j = 0; j < 4; j++) c[mi][ni][j] = 0.f;

    const float* Ag = g_final_rep + (size_t)m0 * H_;

    // precompute per-thread load rows/cols
    int rowi[4], qi[4], gni[4];
#pragma unroll
    for (int i = 0; i < 4; i++) {
        int v = tid + i * 256;
        rowi[i] = v >> 3;
        qi[i]   = (v & 7) * 4;
        int gn = n0 + rowi[i] + 1; if (gn > N_ - 1) gn = N_ - 1;
        gni[i] = gn;
    }

    // prologue: stages 0 and 1
#pragma unroll
    for (int s = 0; s < 2; s++) {
        const uint32_t ab = sA + (uint32_t)s * BM * BKP * 4;
        const uint32_t bb = sB + (uint32_t)s * BN * BKP * 4;
        const int ko = s * BK;
#pragma unroll
        for (int i = 0; i < 4; i++) {
            cpasync16(ab + (uint32_t)(rowi[i] * BKP + qi[i]) * 4,
                      Ag + (size_t)rowi[i] * H_ + ko + qi[i]);
            cpasync16(bb + (uint32_t)(rowi[i] * BKP + qi[i]) * 4,
                      g_embt + (size_t)gni[i] * H_ + ko + qi[i]);
        }
        cp_commit();
    }

#pragma unroll 1
    for (int s = 0; s < H_ / BK; s++) {
        const int buf = s & 1;
        if (s < H_ / BK - 1)
            asm volatile("cp.async.wait_group 1;" ::: "memory");
        else
            asm volatile("cp.async.wait_group 0;" ::: "memory");
        __syncthreads();

        const uint32_t* Au = (const uint32_t*)(Abuf + buf * BM * BKP);
        const uint32_t* Bu = (const uint32_t*)(Bbuf + buf * BN * BKP);
#pragma unroll
        for (int kk = 0; kk < 4; kk++) {
            const int kb = kk * 8;
            uint32_t a[4][4], bfr[4][2];
#pragma unroll
            for (int mi = 0; mi < 4; mi++) {
                int r = wm + mi * 16 + lq;
                a[mi][0] = Au[(r)     * BKP + kb + l4];
                a[mi][1] = Au[(r + 8) * BKP + kb + l4];
                a[mi][2] = Au[(r)     * BKP + kb + l4 + 4];
                a[mi][3] = Au[(r + 8) * BKP + kb + l4 + 4];
            }
#pragma unroll
            for (int ni = 0; ni < 4; ni++) {
                int n = wn + ni * 8 + lq;
                bfr[ni][0] = Bu[n * BKP + kb + l4];
                bfr[ni][1] = Bu[n * BKP + kb + l4 + 4];
            }
#pragma unroll
            for (int mi = 0; mi < 4; mi++)
#pragma unroll
                for (int ni = 0; ni < 4; ni++)
                    mma_tf32(c[mi][ni], a[mi], bfr[ni]);
        }
        __syncthreads();

        if (s + 2 < H_ / BK) {
            const uint32_t ab = sA + (uint32_t)buf * BM * BKP * 4;
            const uint32_t bb = sB + (uint32_t)buf * BN * BKP * 4;
            const int ko = (s + 2) * BK;
#pragma unroll
            for (int i = 0; i < 4; i++) {
                cpasync16(ab + (uint32_t)(rowi[i] * BKP + qi[i]) * 4,
                          Ag + (size_t)rowi[i] * H_ + ko + qi[i]);
                cpasync16(bb + (uint32_t)(rowi[i] * BKP + qi[i]) * 4,
                          g_embt + (size_t)gni[i] * H_ + ko + qi[i]);
            }
            cp_commit();
        }
    }

    // epilogue
    float* so = sm2;   // [128][129]
#pragma unroll
    for (int mi = 0; mi < 4; mi++) {
        int r = wm + mi * 16 + lq;
#pragma unroll
        for (int ni = 0; ni < 4; ni++) {
            int cn = wn + ni * 8 + 2 * l4;
            so[(r)     * 129 + cn]     = c[mi][ni][0];
            so[(r)     * 129 + cn + 1] = c[mi][ni][1];
            so[(r + 8) * 129 + cn]     = c[mi][ni][2];
            so[(r + 8) * 129 + cn + 1] = c[mi][ni][3];
        }
    }
    __syncthreads();

#pragma unroll 8
    for (int i = tid; i < BM * BN; i += 256) {
        int r = i >> 7, cn = i & 127;
        if (n0 + cn < NN_)
            out[(size_t)(m0 + r) * NN_ + n0 + cn] = so[r * 129 + cn];
    }
}

// ---------------------------------------------------------------------------
extern "C" void kernel_launch(void* const* d_in, const int* in_sizes, int n_in,
                              void* d_out, int out_size)
{
    const int*   inputs = (const int*)  d_in[0];
    const float* masks  = (const float*)d_in[1];
    const float* emb    = (const float*)d_in[2];
    const float* Qw     = (const float*)d_in[3];
    const float* Kw     = (const float*)d_in[4];
    const float* lin_w  = (const float*)d_in[5];
    const float* lin_b  = (const float*)d_in[6];

    float* out        = (float*)d_out;
    float* out_scores = out;
    float* out_aff    = out + (size_t)B_ * NN_;

    k0_cvt<<<(N_ * H_ / 4) / 256, 256>>>(emb);

    cudaFuncSetAttribute(k1a_mma,
                         cudaFuncAttributeMaxDynamicSharedMemorySize, K1A_SMEM);
    dim3 g1a(BL_ / BM, (QKN + BN - 1) / BN);
    k1a_mma<<<g1a, 256, K1A_SMEM>>>(inputs, emb, Qw, Kw);

    const int smem1b = (L_*A_*2 + L_*L_ + 64 + 64 + 64 + 16) * 4;
    cudaFuncSetAttribute(k1b_kernel,
                         cudaFuncAttributeMaxDynamicSharedMemorySize, smem1b);
    k1b_kernel<<<B_, 256, smem1b>>>(inputs, masks, emb, out_aff);

    k1c_kernel<<<B_ / 8, 256>>>(lin_w, lin_b);

    cudaFuncSetAttribute(k2_mma,
                         cudaFuncAttributeMaxDynamicSharedMemorySize, GEMM_SMEM);
    dim3 g2(B_ / BM, (NN_ + BN - 1) / BN);
    k2_mma<<<g2, 256, GEMM_SMEM>>>(out_scores);

    (void)in_sizes; (void)n_in; (void)out_size;
}